// round 12
// baseline (speedup 1.0000x reference)
#include <cuda_runtime.h>
#include <cuda_fp16.h>
#include <math.h>
#include <stdint.h>

#define NB 512
#define NL 64
#define ND 1024
#define NU 512
#define NROWS (NB * NL)   // 32768 feature rows

// ---------------------------------------------------------------------------
// Device-global scratch (no allocation allowed)
// ---------------------------------------------------------------------------
__device__ __align__(1024) __half g_fa[(size_t)NROWS * ND];    // 64 MB, fp16 features
__device__ __align__(1024) __half g_W1Th[(size_t)NU * ND];     // [N=512][K=1024] fp16
__device__ float g_h[NB * NU];           // hidden @ W2 + b2
__device__ float g_lp[4 * NROWS];        // per-N-block partial logits

// ---------------------------------------------------------------------------
// PTX helpers (sm_80-era: valid on plain sm_103 target)
// ---------------------------------------------------------------------------
__device__ __forceinline__ uint32_t smem_u32(const void* p) {
    uint32_t a;
    asm("{ .reg .u64 t; cvta.to.shared.u64 t, %1; cvt.u32.u64 %0, t; }" : "=r"(a) : "l"(p));
    return a;
}
__device__ __forceinline__ void cp_async16(uint32_t dst, const void* src) {
    asm volatile("cp.async.cg.shared.global [%0], [%1], 16;" :: "r"(dst), "l"(src) : "memory");
}
__device__ __forceinline__ void cp_commit() {
    asm volatile("cp.async.commit_group;" ::: "memory");
}
template <int N> __device__ __forceinline__ void cp_wait() {
    asm volatile("cp.async.wait_group %0;" :: "n"(N) : "memory");
}
__device__ __forceinline__ void ldsm_x4(uint32_t* r, uint32_t addr) {
    asm volatile("ldmatrix.sync.aligned.m8n8.x4.shared.b16 {%0,%1,%2,%3}, [%4];"
                 : "=r"(r[0]), "=r"(r[1]), "=r"(r[2]), "=r"(r[3]) : "r"(addr));
}
__device__ __forceinline__ void mma_f16(float* c, const uint32_t* a, const uint32_t* b) {
    asm volatile(
        "mma.sync.aligned.m16n8k16.row.col.f32.f16.f16.f32 "
        "{%0,%1,%2,%3}, {%4,%5,%6,%7}, {%8,%9}, {%0,%1,%2,%3};"
        : "+f"(c[0]), "+f"(c[1]), "+f"(c[2]), "+f"(c[3])
        : "r"(a[0]), "r"(a[1]), "r"(a[2]), "r"(a[3]), "r"(b[0]), "r"(b[1]));
}

// fast tanh: 1 - 2/(exp2(2*log2e*x)+1); rel err ~1e-6. Saturates correctly.
__device__ __forceinline__ float tanh_fast(float x) {
    float e;
    asm("ex2.approx.f32 %0, %1;" : "=f"(e) : "f"(x * 2.88539008177792681f));
    float r;
    asm("rcp.approx.f32 %0, %1;" : "=f"(r) : "f"(e + 1.0f));
    return 1.0f - 2.0f * r;
}

// ---------------------------------------------------------------------------
// kprep: k1 (h = hidden @ W2 + b2) + kconvW (W1 -> W1T fp16). 640 blocks.
// ---------------------------------------------------------------------------
#define PREP_K1   128
#define PREP_KW   512
#define PREP_GRID (PREP_K1 + PREP_KW)

__global__ __launch_bounds__(256) void kprep(
    const float* __restrict__ hidden, const float* __restrict__ W1,
    const float* __restrict__ W2,     const float* __restrict__ b2)
{
    __shared__ __align__(16) char sm[13056];
    const int bid = blockIdx.x;
    const int tid = threadIdx.x;

    if (bid >= PREP_K1) {
        // ---- kconvW: W1 [K,N] fp32 -> W1T [N,K] fp16 (32x32 tiles) ----
        float (*t)[33] = (float (*)[33])sm;
        int b  = bid - PREP_K1;
        int n0 = (b & 15) * 32, k0 = (b >> 4) * 32;
        int tx = tid & 31, ty = tid >> 5;   // 32 x 8
        #pragma unroll
        for (int i = 0; i < 32; i += 8)
            t[ty + i][tx] = W1[(size_t)(k0 + ty + i) * NU + n0 + tx];
        __syncthreads();
        #pragma unroll
        for (int i = 0; i < 32; i += 8) {
            float v = t[tx][ty + i];                 // = W1[k0+tx][n0+ty+i]
            g_W1Th[(size_t)(n0 + ty + i) * ND + k0 + tx] = __float2half_rn(v);
        }
        return;
    }

    // ---- k1: h = hidden @ W2 + b2 (512x512x512 fp32, 32x64 tiles) ----
    {
        float (*Xs)[33] = (float (*)[33])sm;                 // [32k][32row]
        float (*Ws)[68] = (float (*)[68])(sm + 4224);        // [32k][64col]
        const int tx = tid & 15, ty = tid >> 4;              // 16 x 16
        const int rowB = (bid >> 3) * 32;
        const int nB   = (bid & 7) * 64;
        float acc[2][4] = {};

        for (int k0 = 0; k0 < NU; k0 += 32) {
            {   // X tile 32x32: 1 float4 per thread, stored transposed
                int r = tid >> 3, c4 = (tid & 7) * 4;
                float4 v = *(const float4*)(hidden + (size_t)(rowB + r) * NU + k0 + c4);
                Xs[c4 + 0][r] = v.x; Xs[c4 + 1][r] = v.y;
                Xs[c4 + 2][r] = v.z; Xs[c4 + 3][r] = v.w;
            }
            #pragma unroll
            for (int p = 0; p < 2; ++p) {   // W tile 32x64: 2 float4 per thread
                int k = (tid >> 4) + p * 16, c4 = (tid & 15) * 4;
                *(float4*)&Ws[k][c4] =
                    *(const float4*)(W2 + (size_t)(k0 + k) * NU + nB + c4);
            }
            __syncthreads();
            #pragma unroll
            for (int k = 0; k < 32; ++k) {
                float a0 = Xs[k][ty * 2], a1 = Xs[k][ty * 2 + 1];
                float4 b = *(const float4*)&Ws[k][tx * 4];
                float bn[4] = {b.x, b.y, b.z, b.w};
                #pragma unroll
                for (int j = 0; j < 4; ++j) {
                    acc[0][j] = fmaf(a0, bn[j], acc[0][j]);
                    acc[1][j] = fmaf(a1, bn[j], acc[1][j]);
                }
            }
            __syncthreads();
        }
        #pragma unroll
        for (int i = 0; i < 2; ++i)
            #pragma unroll
            for (int j = 0; j < 4; ++j)
                g_h[(size_t)(rowB + ty * 2 + i) * NU + nB + tx * 4 + j] =
                    acc[i][j] + b2[nB + tx * 4 + j];
    }
}

// ---------------------------------------------------------------------------
// k2: fp16 mma.sync GEMM with IN-KERNEL fp32->fp16 A conversion.
// BM=128, BN=128, BK=32. 128 threads (4 warps: 2M x 2N, warp tile 64x64).
// A: LDG fp32 from features, convert, STS fp16 (4 subgroups interleaved with
//    MMA phases so L2 latency hides). W: 3-stage cp.async.
// N-tile-0 CTAs also STG converted fp16 to g_fa for k34.
// Grid (4 N, 256 M), N fastest -> A blocks L2-shared within a wave.
// 3 CTAs/SM (smem ~64KB, regs capped 170). 80B rows: ldmatrix conflict-free.
// ---------------------------------------------------------------------------
#define ROWB 80
#define TILE_B (128 * ROWB)      // 10240 bytes per tile
#define STG_B  (2 * TILE_B)      // A(fp16), Wh
#define STAGES 3
#define NCHUNK (ND / 32)
#define HS_OFF   (STAGES * STG_B)          // 2 x 128 floats
#define VS_OFF   (HS_OFF + 1024)           // 128 floats
#define PART_OFF (VS_OFF + 512)            // 128 x 2 floats
#define SMEM_K2  (PART_OFF + 1024)

__global__ __launch_bounds__(128, 3) void k2_score_gemm(
    const float* __restrict__ features,
    const float* __restrict__ b1, const float* __restrict__ Vw)
{
    extern __shared__ __align__(1024) char smem[];
    const uint32_t sb = smem_u32(smem);
    const int tid  = threadIdx.x;
    const int lane = tid & 31, wid = tid >> 5;
    const int wm = wid >> 1, wn = wid & 1;     // 2 x 2 warp grid, 64x64 tiles
    const int nB   = blockIdx.x * 128;         // N fastest
    const int rowB = blockIdx.y * 128;
    const bool write_fa = (blockIdx.x == 0);

    float* hs   = (float*)(smem + HS_OFF);    // [2][128]
    float* Vs   = (float*)(smem + VS_OFF);    // [128]
    float* part = (float*)(smem + PART_OFF);  // [128][2]

    // epilogue constants (2 per thread)
    {
        int i0 = tid, i1 = tid + 128;
        hs[i0] = g_h[(size_t)(blockIdx.y * 2) * NU + nB + i0] + b1[nB + i0];
        hs[i1] = g_h[(size_t)(blockIdx.y * 2 + 1) * NU + nB + (i1 - 128)] + b1[nB + (i1 - 128)];
        Vs[tid] = Vw[nB + tid];
    }

    const float*  fsrc = features + (size_t)rowB * ND;
    const __half* wsrc = g_W1Th  + (size_t)nB   * ND;

    // W loader: 512 x 16B chunks, 4 per thread (cp.async)
    auto load_W = [&](int s, int kc) {
        uint32_t sdst = sb + s * STG_B + TILE_B;
        #pragma unroll
        for (int i = 0; i < 4; ++i) {
            int idx = tid + i * 128;
            int row = idx >> 2, ch = idx & 3;
            cp_async16(sdst + row * ROWB + ch * 16,
                       wsrc + (size_t)row * ND + kc * 32 + ch * 8);
        }
        cp_commit();
    };

    // A producer: group g (0..3) covers 2 float4 per thread (rows g*32..g*32+31)
    auto ldgA2 = [&](int g, int kc, float4* v) {
        #pragma unroll
        for (int i = 0; i < 2; ++i) {
            int idx = tid + (g * 2 + i) * 128;
            int row = idx >> 3, ch = idx & 7;
            v[i] = *(const float4*)(fsrc + (size_t)row * ND + kc * 32 + ch * 4);
        }
    };
    auto stsA2 = [&](int g, int st, int kc, const float4* v) {
        #pragma unroll
        for (int i = 0; i < 2; ++i) {
            int idx = tid + (g * 2 + i) * 128;
            int row = idx >> 3, ch = idx & 7;
            __half2 h0 = __floats2half2_rn(v[i].x, v[i].y);
            __half2 h1 = __floats2half2_rn(v[i].z, v[i].w);
            uint2 pk = make_uint2(*(const uint32_t*)&h0, *(const uint32_t*)&h1);
            *(uint2*)(smem + st * STG_B + row * ROWB + ch * 8) = pk;
            if (write_fa)
                *(uint2*)((char*)g_fa +
                          ((size_t)(rowB + row) * ND + kc * 32 + ch * 4) * 2) = pk;
        }
    };

    // prologue: W stages 0,1 via cp.async; A stages 0,1 synchronously
    load_W(0, 0);
    load_W(1, 1);
    #pragma unroll
    for (int s = 0; s < 2; ++s) {
        #pragma unroll
        for (int g = 0; g < 4; ++g) {
            float4 v[2];
            ldgA2(g, s, v);
            stsA2(g, s, s, v);
        }
    }

    float acc[4][8][4] = {};    // [mt 16-row][nt 8-col][vals]

    // precomputed ldmatrix intra-warp offsets
    const int a_row = ((lane >> 3) & 1) * 8 + (lane & 7);
    const int a_ch  = (lane >> 4);
    const int b_row = (lane >> 4) * 8 + (lane & 7);
    const int b_ch  = ((lane >> 3) & 1);

    for (int c = 0; c < NCHUNK; ++c) {
        int s = c % STAGES;
        cp_wait<1>();            // W for chunk c has landed
        __syncthreads();         // all warps done with stage (c-1)%3; A STS visible

        int tc = c + 2;
        int st = tc % STAGES;
        bool prod = tc < NCHUNK;
        if (prod) load_W(st, tc);
        else cp_commit();        // keep wait_group counts consistent

        uint32_t aB  = sb + s * STG_B;
        uint32_t whB = aB + TILE_B;

        float4 va[2];
        if (prod) ldgA2(0, tc, va);

        #pragma unroll
        for (int kk = 0; kk < 2; ++kk) {
            uint32_t a[4][4], bh[8][2];
            #pragma unroll
            for (int mt = 0; mt < 4; ++mt) {
                int r  = wm * 64 + mt * 16 + a_row;
                int ch = kk * 2 + a_ch;
                ldsm_x4(a[mt], aB + r * ROWB + ch * 16);
            }
            #pragma unroll
            for (int ntp = 0; ntp < 4; ++ntp) {
                int r  = wn * 64 + ntp * 16 + b_row;
                int ch = kk * 2 + b_ch;
                uint32_t t0[4];
                ldsm_x4(t0, whB + r * ROWB + ch * 16);
                bh[ntp*2][0] = t0[0]; bh[ntp*2][1] = t0[1];
                bh[ntp*2+1][0] = t0[2]; bh[ntp*2+1][1] = t0[3];
            }
            // producer: store previous group, load next (hidden under MMAs)
            if (prod) {
                stsA2(kk * 2, st, tc, va);
                ldgA2(kk * 2 + 1, tc, va);
            }
            #pragma unroll
            for (int mt = 0; mt < 4; ++mt)
                #pragma unroll
                for (int nt = 0; nt < 8; ++nt)
                    mma_f16(acc[mt][nt], a[mt], bh[nt]);
            if (prod) {
                stsA2(kk * 2 + 1, st, tc, va);
                if (kk == 0) ldgA2(2, tc, va);
            }
        }
    }

    // Fused epilogue: tanh(acc + b1 + h) . V  -> partial logits
    const int g = lane >> 2, tg4 = lane & 3;
    const int bloc = wm;               // warp tile 64 rows == one batch (L=64)
    #pragma unroll
    for (int mt = 0; mt < 4; ++mt) {
        float s0 = 0.f, s1 = 0.f;
        #pragma unroll
        for (int nt = 0; nt < 8; ++nt) {
            #pragma unroll
            for (int c2 = 0; c2 < 2; ++c2) {
                int col = wn * 64 + nt * 8 + tg4 * 2 + c2;
                float hb = hs[bloc * 128 + col];
                float vw = Vs[col];
                s0 = fmaf(tanh_fast(acc[mt][nt][c2]     + hb), vw, s0);
                s1 = fmaf(tanh_fast(acc[mt][nt][2 + c2] + hb), vw, s1);
            }
        }
        s0 += __shfl_xor_sync(0xFFFFFFFFu, s0, 1);
        s0 += __shfl_xor_sync(0xFFFFFFFFu, s0, 2);
        s1 += __shfl_xor_sync(0xFFFFFFFFu, s1, 1);
        s1 += __shfl_xor_sync(0xFFFFFFFFu, s1, 2);
        if (tg4 == 0) {
            int r0 = wm * 64 + mt * 16 + g;
            part[r0 * 2 + wn]       = s0;
            part[(r0 + 8) * 2 + wn] = s1;
        }
    }
    __syncthreads();
    g_lp[(size_t)blockIdx.x * NROWS + rowB + tid] = part[tid*2] + part[tid*2+1];
}

// ---------------------------------------------------------------------------
// k34: fused softmax (warp 0) + context (all 256 threads). One block/batch.
// ---------------------------------------------------------------------------
__global__ __launch_bounds__(256) void k34_softmax_context(
    float* __restrict__ out_attn, float* __restrict__ ctx)
{
    int b = blockIdx.x;
    __shared__ float as[64];

    if (threadIdx.x < 32) {
        int lane = threadIdx.x;
        float x1 = 0.f, x2 = 0.f;
        #pragma unroll
        for (int p = 0; p < 4; ++p) {
            x1 += g_lp[(size_t)p * NROWS + b * 64 + lane];
            x2 += g_lp[(size_t)p * NROWS + b * 64 + lane + 32];
        }
        float m = fmaxf(x1, x2);
        #pragma unroll
        for (int o = 16; o > 0; o >>= 1)
            m = fmaxf(m, __shfl_xor_sync(0xFFFFFFFFu, m, o));
        float e1 = expf(x1 - m), e2 = expf(x2 - m);
        float s = e1 + e2;
        #pragma unroll
        for (int o = 16; o > 0; o >>= 1)
            s += __shfl_xor_sync(0xFFFFFFFFu, s, o);
        float inv = 1.f / s;
        float a1 = e1 * inv, a2 = e2 * inv;
        as[lane]      = a1;
        as[lane + 32] = a2;
        out_attn[b * 64 + lane]      = a1;
        out_attn[b * 64 + lane + 32] = a2;
    }
    __syncthreads();

    const __half* Xb = g_fa + (size_t)b * NL * ND;
    int c = threadIdx.x * 4;             // 4 halves per thread, 256 thr = 1024
    float4 acc = make_float4(0.f, 0.f, 0.f, 0.f);
    #pragma unroll 8
    for (int l = 0; l < NL; ++l) {
        float a = as[l];
        uint2 p = *(const uint2*)(Xb + (size_t)l * ND + c);
        float2 f0 = __half22float2(*(__half2*)&p.x);
        float2 f1 = __half22float2(*(__half2*)&p.y);
        acc.x = fmaf(a, f0.x, acc.x);
        acc.y = fmaf(a, f0.y, acc.y);
        acc.z = fmaf(a, f1.x, acc.z);
        acc.w = fmaf(a, f1.y, acc.w);
    }
    *(float4*)(ctx + (size_t)b * ND + c) = acc;
}

// ---------------------------------------------------------------------------
extern "C" void kernel_launch(void* const* d_in, const int* in_sizes, int n_in,
                              void* d_out, int out_size)
{
    const float* features = (const float*)d_in[0];
    const float* hidden   = (const float*)d_in[1];
    const float* W1_w     = (const float*)d_in[2];
    const float* W1_b     = (const float*)d_in[3];
    const float* W2_w     = (const float*)d_in[4];
    const float* W2_b     = (const float*)d_in[5];
    const float* V_w      = (const float*)d_in[6];
    // d_in[7] = V_b: unused (softmax shift-invariant)

    float* out  = (float*)d_out;
    float* ctx  = out;
    float* attn = out + (size_t)NB * ND;

    cudaFuncSetAttribute(k2_score_gemm,
                         cudaFuncAttributeMaxDynamicSharedMemorySize, SMEM_K2);

    kprep<<<PREP_GRID, 256>>>(hidden, W1_w, W2_w, W2_b);
    k2_score_gemm<<<dim3(NU / 128, NROWS / 128), 128, SMEM_K2>>>(features, W1_b, V_w);
    k34_softmax_context<<<NB, 256>>>(attn, ctx);
}

// round 13
// speedup vs baseline: 2.2672x; 2.2672x over previous
#include <cuda_runtime.h>
#include <cuda_fp16.h>
#include <math.h>
#include <stdint.h>

#define NB 512
#define NL 64
#define ND 1024
#define NU 512
#define NROWS (NB * NL)   // 32768 feature rows

// ---------------------------------------------------------------------------
// Device-global scratch (no allocation allowed)
// ---------------------------------------------------------------------------
__device__ __align__(1024) __half g_fa[(size_t)NROWS * ND];    // 64 MB, fp16 features
__device__ __align__(1024) __half g_W1Th[(size_t)NU * ND];     // [N=512][K=1024] fp16
__device__ float g_h[NB * NU];           // hidden @ W2 + b2
__device__ float g_lp[4 * NROWS];        // per-N-block partial logits

// ---------------------------------------------------------------------------
// PTX helpers (sm_80-era: valid on plain sm_103 target)
// ---------------------------------------------------------------------------
__device__ __forceinline__ uint32_t smem_u32(const void* p) {
    uint32_t a;
    asm("{ .reg .u64 t; cvta.to.shared.u64 t, %1; cvt.u32.u64 %0, t; }" : "=r"(a) : "l"(p));
    return a;
}
__device__ __forceinline__ void cp_async16(uint32_t dst, const void* src) {
    asm volatile("cp.async.cg.shared.global [%0], [%1], 16;" :: "r"(dst), "l"(src) : "memory");
}
__device__ __forceinline__ void cp_commit() {
    asm volatile("cp.async.commit_group;" ::: "memory");
}
template <int N> __device__ __forceinline__ void cp_wait() {
    asm volatile("cp.async.wait_group %0;" :: "n"(N) : "memory");
}
__device__ __forceinline__ void ldsm_x4(uint32_t* r, uint32_t addr) {
    asm volatile("ldmatrix.sync.aligned.m8n8.x4.shared.b16 {%0,%1,%2,%3}, [%4];"
                 : "=r"(r[0]), "=r"(r[1]), "=r"(r[2]), "=r"(r[3]) : "r"(addr));
}
__device__ __forceinline__ void mma_f16(float* c, const uint32_t* a, const uint32_t* b) {
    asm volatile(
        "mma.sync.aligned.m16n8k16.row.col.f32.f16.f16.f32 "
        "{%0,%1,%2,%3}, {%4,%5,%6,%7}, {%8,%9}, {%0,%1,%2,%3};"
        : "+f"(c[0]), "+f"(c[1]), "+f"(c[2]), "+f"(c[3])
        : "r"(a[0]), "r"(a[1]), "r"(a[2]), "r"(a[3]), "r"(b[0]), "r"(b[1]));
}

// fast tanh: 1 - 2/(exp2(2*log2e*x)+1); rel err ~1e-6. Saturates correctly.
__device__ __forceinline__ float tanh_fast(float x) {
    float e;
    asm("ex2.approx.f32 %0, %1;" : "=f"(e) : "f"(x * 2.88539008177792681f));
    float r;
    asm("rcp.approx.f32 %0, %1;" : "=f"(r) : "f"(e + 1.0f));
    return 1.0f - 2.0f * r;
}

// ---------------------------------------------------------------------------
// kprep: fused prepass. One launch, three block roles (scheduled in order):
//   blocks [0,128)       : k1  h = hidden @ W2 + b2  (32x64 tiles, 128 CTAs)
//   blocks [128,640)     : kconvW  W1 -> W1T fp16 transpose
//   blocks [640,8832)    : kconvA  features fp32 -> fp16 (16 elem/thread,
//                          streaming cache hints: __ldcs read / __stcs write)
// ---------------------------------------------------------------------------
#define PREP_K1   128
#define PREP_KW   512
#define PREP_KA   8192
#define PREP_GRID (PREP_K1 + PREP_KW + PREP_KA)

__global__ __launch_bounds__(256) void kprep(
    const float* __restrict__ features, const float* __restrict__ hidden,
    const float* __restrict__ W1,       const float* __restrict__ W2,
    const float* __restrict__ b2)
{
    __shared__ __align__(16) char sm[13056];
    const int bid = blockIdx.x;
    const int tid = threadIdx.x;

    if (bid >= PREP_K1 + PREP_KW) {
        // ---- kconvA: fp32 -> fp16, 16 elements per thread, MLP=4 ----
        // Read-once fp32 stream: __ldcs (evict-first). Write stream: __stcs.
        size_t base = (size_t)(bid - PREP_K1 - PREP_KW) * 4096;
        #pragma unroll
        for (int s2 = 0; s2 < 4; ++s2) {
            size_t i = base + (size_t)s2 * 1024 + (size_t)tid * 4;
            float4 v = __ldcs((const float4*)(features + i));
            __half2 p0 = __floats2half2_rn(v.x, v.y);
            __half2 p1 = __floats2half2_rn(v.z, v.w);
            __stcs((uint2*)((char*)g_fa + i * 2),
                   make_uint2(*(uint32_t*)&p0, *(uint32_t*)&p1));
        }
        return;
    }

    if (bid >= PREP_K1) {
        // ---- kconvW: W1 [K,N] fp32 -> W1T [N,K] fp16 (32x32 tiles) ----
        float (*t)[33] = (float (*)[33])sm;
        int b  = bid - PREP_K1;
        int n0 = (b & 15) * 32, k0 = (b >> 4) * 32;
        int tx = tid & 31, ty = tid >> 5;   // 32 x 8
        #pragma unroll
        for (int i = 0; i < 32; i += 8)
            t[ty + i][tx] = W1[(size_t)(k0 + ty + i) * NU + n0 + tx];
        __syncthreads();
        #pragma unroll
        for (int i = 0; i < 32; i += 8) {
            float v = t[tx][ty + i];                 // = W1[k0+tx][n0+ty+i]
            g_W1Th[(size_t)(n0 + ty + i) * ND + k0 + tx] = __float2half_rn(v);
        }
        return;
    }

    // ---- k1: h = hidden @ W2 + b2 (512x512x512 fp32, 32x64 tiles) ----
    {
        float (*Xs)[33] = (float (*)[33])sm;                 // [32k][32row]
        float (*Ws)[68] = (float (*)[68])(sm + 4224);        // [32k][64col]
        const int tx = tid & 15, ty = tid >> 4;              // 16 x 16
        const int rowB = (bid >> 3) * 32;
        const int nB   = (bid & 7) * 64;
        float acc[2][4] = {};

        for (int k0 = 0; k0 < NU; k0 += 32) {
            {   // X tile 32x32: 1 float4 per thread, stored transposed
                int r = tid >> 3, c4 = (tid & 7) * 4;
                float4 v = *(const float4*)(hidden + (size_t)(rowB + r) * NU + k0 + c4);
                Xs[c4 + 0][r] = v.x; Xs[c4 + 1][r] = v.y;
                Xs[c4 + 2][r] = v.z; Xs[c4 + 3][r] = v.w;
            }
            #pragma unroll
            for (int p = 0; p < 2; ++p) {   // W tile 32x64: 2 float4 per thread
                int k = (tid >> 4) + p * 16, c4 = (tid & 15) * 4;
                *(float4*)&Ws[k][c4] =
                    *(const float4*)(W2 + (size_t)(k0 + k) * NU + nB + c4);
            }
            __syncthreads();
            #pragma unroll
            for (int k = 0; k < 32; ++k) {
                float a0 = Xs[k][ty * 2], a1 = Xs[k][ty * 2 + 1];
                float4 b = *(const float4*)&Ws[k][tx * 4];
                float bn[4] = {b.x, b.y, b.z, b.w};
                #pragma unroll
                for (int j = 0; j < 4; ++j) {
                    acc[0][j] = fmaf(a0, bn[j], acc[0][j]);
                    acc[1][j] = fmaf(a1, bn[j], acc[1][j]);
                }
            }
            __syncthreads();
        }
        #pragma unroll
        for (int i = 0; i < 2; ++i)
            #pragma unroll
            for (int j = 0; j < 4; ++j)
                g_h[(size_t)(rowB + ty * 2 + i) * NU + nB + tx * 4 + j] =
                    acc[i][j] + b2[nB + tx * 4 + j];
    }
}

// ---------------------------------------------------------------------------
// k2: fp16 mma.sync GEMM, single term (A.Wh), fused epilogue.
// BM=128, BN=128, BK=32. 128 threads (4 warps: 2M x 2N, warp tile 64x64).
// 3-stage cp.async multistage, one barrier per chunk.
// 3 CTAs/SM (smem 64.0KB, regs capped 170) -> 12 warps/SM for latency hiding.
// 80B rows: ldmatrix conflict-free.  [R11 version — proven 163.7us total]
// ---------------------------------------------------------------------------
#define ROWB 80
#define TILE_B (128 * ROWB)      // 10240 bytes per tile
#define STG_B  (2 * TILE_B)      // A, Wh
#define STAGES 3
#define NCHUNK (ND / 32)
#define HS_OFF   (STAGES * STG_B)          // 2 x 128 floats
#define VS_OFF   (HS_OFF + 1024)           // 128 floats
#define PART_OFF (VS_OFF + 512)            // 128 x 2 floats
#define SMEM_K2  (PART_OFF + 1024)

__global__ __launch_bounds__(128, 3) void k2_score_gemm(
    const float* __restrict__ b1, const float* __restrict__ Vw)
{
    extern __shared__ __align__(1024) char smem[];
    const uint32_t sb = smem_u32(smem);
    const int tid  = threadIdx.x;
    const int lane = tid & 31, wid = tid >> 5;
    const int wm = wid >> 1, wn = wid & 1;     // 2 x 2 warp grid, 64x64 tiles
    const int rowB = blockIdx.x * 128;
    const int nB   = blockIdx.y * 128;

    float* hs   = (float*)(smem + HS_OFF);    // [2][128]
    float* Vs   = (float*)(smem + VS_OFF);    // [128]
    float* part = (float*)(smem + PART_OFF);  // [128][2]

    // epilogue constants (2 per thread)
    {
        int i0 = tid, i1 = tid + 128;
        hs[i0] = g_h[(size_t)(blockIdx.x * 2) * NU + nB + i0] + b1[nB + i0];
        hs[i1] = g_h[(size_t)(blockIdx.x * 2 + 1) * NU + nB + (i1 - 128)] + b1[nB + (i1 - 128)];
        Vs[tid] = Vw[nB + tid];
    }

    const __half* base0 = g_fa   + (size_t)rowB * ND;
    const __half* base1 = g_W1Th + (size_t)nB   * ND;

    // stage loader: 1024 x 16B chunks, 8 per thread
    auto load_stage = [&](int s, int kc) {
        uint32_t sdst = sb + s * STG_B;
        #pragma unroll
        for (int i = 0; i < 8; ++i) {
            int idx  = tid + i * 128;
            int tile = idx >> 9;               // 512 chunks per tile
            int rem  = idx & 511;
            int row  = rem >> 2, ch = rem & 3;
            const __half* gb = (tile == 0) ? base0 : base1;
            cp_async16(sdst + tile * TILE_B + row * ROWB + ch * 16,
                       gb + (size_t)row * ND + kc * 32 + ch * 8);
        }
        cp_commit();
    };

    // prologue: fill 2 of the 3 stages (chunk c issues chunk c+2)
    load_stage(0, 0);
    load_stage(1, 1);

    float acc[4][8][4] = {};    // [mt 16-row][nt 8-col][vals]

    // precomputed ldmatrix intra-warp offsets
    const int a_row = ((lane >> 3) & 1) * 8 + (lane & 7);
    const int a_ch  = (lane >> 4);
    const int b_row = (lane >> 4) * 8 + (lane & 7);
    const int b_ch  = ((lane >> 3) & 1);

    for (int c = 0; c < NCHUNK; ++c) {
        int s = c % STAGES;
        cp_wait<1>();            // chunk c's stage has landed
        __syncthreads();         // all warps done reading stage (c-1)%3

        // issue next loads NOW (into the stage retired last chunk) so the
        // LDGSTS issue burst overlaps with this chunk's MMA phase
        if (c + 2 < NCHUNK) load_stage((c + 2) % STAGES, c + 2);
        else cp_commit();        // keep wait_group counts consistent

        uint32_t aB  = sb + s * STG_B;
        uint32_t whB = aB + TILE_B;

        #pragma unroll
        for (int kk = 0; kk < 2; ++kk) {
            uint32_t a[4][4], bh[8][2];
            #pragma unroll
            for (int mt = 0; mt < 4; ++mt) {
                int r  = wm * 64 + mt * 16 + a_row;
                int ch = kk * 2 + a_ch;
                ldsm_x4(a[mt], aB + r * ROWB + ch * 16);
            }
            #pragma unroll
            for (int ntp = 0; ntp < 4; ++ntp) {
                int r  = wn * 64 + ntp * 16 + b_row;
                int ch = kk * 2 + b_ch;
                uint32_t t0[4];
                ldsm_x4(t0, whB + r * ROWB + ch * 16);
                bh[ntp*2][0] = t0[0]; bh[ntp*2][1] = t0[1];
                bh[ntp*2+1][0] = t0[2]; bh[ntp*2+1][1] = t0[3];
            }
            #pragma unroll
            for (int mt = 0; mt < 4; ++mt)
                #pragma unroll
                for (int nt = 0; nt < 8; ++nt)
                    mma_f16(acc[mt][nt], a[mt], bh[nt]);
        }
    }

    // Fused epilogue: tanh(acc + b1 + h) . V  -> partial logits
    const int g = lane >> 2, tg4 = lane & 3;
    const int bloc = wm;               // warp tile 64 rows == one batch (L=64)
    #pragma unroll
    for (int mt = 0; mt < 4; ++mt) {
        float s0 = 0.f, s1 = 0.f;
        #pragma unroll
        for (int nt = 0; nt < 8; ++nt) {
            #pragma unroll
            for (int c2 = 0; c2 < 2; ++c2) {
                int col = wn * 64 + nt * 8 + tg4 * 2 + c2;
                float hb = hs[bloc * 128 + col];
                float vw = Vs[col];
                s0 = fmaf(tanh_fast(acc[mt][nt][c2]     + hb), vw, s0);
                s1 = fmaf(tanh_fast(acc[mt][nt][2 + c2] + hb), vw, s1);
            }
        }
        s0 += __shfl_xor_sync(0xFFFFFFFFu, s0, 1);
        s0 += __shfl_xor_sync(0xFFFFFFFFu, s0, 2);
        s1 += __shfl_xor_sync(0xFFFFFFFFu, s1, 1);
        s1 += __shfl_xor_sync(0xFFFFFFFFu, s1, 2);
        if (tg4 == 0) {
            int r0 = wm * 64 + mt * 16 + g;
            part[r0 * 2 + wn]       = s0;
            part[(r0 + 8) * 2 + wn] = s1;
        }
    }
    __syncthreads();
    g_lp[(size_t)blockIdx.y * NROWS + rowB + tid] = part[tid*2] + part[tid*2+1];
}

// ---------------------------------------------------------------------------
// k34: fused softmax (warp 0) + context (all 256 threads). One block/batch.
// ---------------------------------------------------------------------------
__global__ __launch_bounds__(256) void k34_softmax_context(
    float* __restrict__ out_attn, float* __restrict__ ctx)
{
    int b = blockIdx.x;
    __shared__ float as[64];

    if (threadIdx.x < 32) {
        int lane = threadIdx.x;
        float x1 = 0.f, x2 = 0.f;
        #pragma unroll
        for (int p = 0; p < 4; ++p) {
            x1 += g_lp[(size_t)p * NROWS + b * 64 + lane];
            x2 += g_lp[(size_t)p * NROWS + b * 64 + lane + 32];
        }
        float m = fmaxf(x1, x2);
        #pragma unroll
        for (int o = 16; o > 0; o >>= 1)
            m = fmaxf(m, __shfl_xor_sync(0xFFFFFFFFu, m, o));
        float e1 = expf(x1 - m), e2 = expf(x2 - m);
        float s = e1 + e2;
        #pragma unroll
        for (int o = 16; o > 0; o >>= 1)
            s += __shfl_xor_sync(0xFFFFFFFFu, s, o);
        float inv = 1.f / s;
        float a1 = e1 * inv, a2 = e2 * inv;
        as[lane]      = a1;
        as[lane + 32] = a2;
        out_attn[b * 64 + lane]      = a1;
        out_attn[b * 64 + lane + 32] = a2;
    }
    __syncthreads();

    const __half* Xb = g_fa + (size_t)b * NL * ND;
    int c = threadIdx.x * 4;             // 4 halves per thread, 256 thr = 1024
    float4 acc = make_float4(0.f, 0.f, 0.f, 0.f);
    #pragma unroll 8
    for (int l = 0; l < NL; ++l) {
        float a = as[l];
        uint2 p = *(const uint2*)(Xb + (size_t)l * ND + c);
        float2 f0 = __half22float2(*(__half2*)&p.x);
        float2 f1 = __half22float2(*(__half2*)&p.y);
        acc.x = fmaf(a, f0.x, acc.x);
        acc.y = fmaf(a, f0.y, acc.y);
        acc.z = fmaf(a, f1.x, acc.z);
        acc.w = fmaf(a, f1.y, acc.w);
    }
    *(float4*)(ctx + (size_t)b * ND + c) = acc;
}

// ---------------------------------------------------------------------------
extern "C" void kernel_launch(void* const* d_in, const int* in_sizes, int n_in,
                              void* d_out, int out_size)
{
    const float* features = (const float*)d_in[0];
    const float* hidden   = (const float*)d_in[1];
    const float* W1_w     = (const float*)d_in[2];
    const float* W1_b     = (const float*)d_in[3];
    const float* W2_w     = (const float*)d_in[4];
    const float* W2_b     = (const float*)d_in[5];
    const float* V_w      = (const float*)d_in[6];
    // d_in[7] = V_b: unused (softmax shift-invariant)

    float* out  = (float*)d_out;
    float* ctx  = out;
    float* attn = out + (size_t)NB * ND;

    cudaFuncSetAttribute(k2_score_gemm,
                         cudaFuncAttributeMaxDynamicSharedMemorySize, SMEM_K2);

    kprep<<<PREP_GRID, 256>>>(features, hidden, W1_w, W2_w, W2_b);
    k2_score_gemm<<<dim3(NROWS / 128, NU / 128), 128, SMEM_K2>>>(W1_b, V_w);
    k34_softmax_context<<<NB, 256>>>(attn, ctx);
}